// round 1
// baseline (speedup 1.0000x reference)
#include <cuda_runtime.h>
#include <math.h>

// Problem constants (match reference)
#define H        2048
#define E        64
#define TOPK     2
#define TM       64        // tokens per block
#define KB       32        // K-chunk
#define THREADS  256

// Loss scratch (no allocations allowed -> __device__ globals, zeroed each launch)
__device__ float g_eload[E];
__device__ float g_zsum;

__global__ void zero_kernel() {
    int t = threadIdx.x;
    if (t < E) g_eload[t] = 0.0f;
    if (t == 0) g_zsum = 0.0f;
}

__global__ __launch_bounds__(THREADS) void gate_kernel(
    const float* __restrict__ x,   // [N, H]
    const float* __restrict__ W,   // [E, H]
    float* __restrict__ out,       // [2N scores][2N idx][1 loss]
    int N)
{
    __shared__ __align__(16) union {
        struct {
            float xs[TM][KB + 1];   // +1 pad: conflict-free broadcast reads
            float ws[KB][E + 4];    // k-major W tile, +4 pad keeps 16B align
        } g;
        float ls[TM][E + 1];        // logits/scores for epilogue
    } sm;
    __shared__ float zsum;

    const int tid  = threadIdx.x;
    const int r    = tid >> 3;       // 0..31 : token pair index
    const int gq   = tid & 7;        // 0..7  : expert group
    const int r2   = r * 2;
    const int g8   = gq * 8;
    const int tok0 = blockIdx.x * TM;

    float acc[2][8];
#pragma unroll
    for (int i = 0; i < 2; i++)
#pragma unroll
        for (int e = 0; e < 8; e++) acc[i][e] = 0.0f;

    for (int k0 = 0; k0 < H; k0 += KB) {
        // ---- load x tile [TM x KB] (float4 global, scalar smem stores) ----
#pragma unroll
        for (int it = 0; it < 2; it++) {
            int qq = tid + it * 256;           // 0..511 float4 slots
            int t  = qq >> 3;
            int kq = (qq & 7) * 4;
            float4 v = *reinterpret_cast<const float4*>(
                &x[(size_t)(tok0 + t) * H + k0 + kq]);
            sm.g.xs[t][kq + 0] = v.x;
            sm.g.xs[t][kq + 1] = v.y;
            sm.g.xs[t][kq + 2] = v.z;
            sm.g.xs[t][kq + 3] = v.w;
        }
        // ---- load W tile transposed into k-major [KB x E] ----
#pragma unroll
        for (int it = 0; it < 2; it++) {
            int qq = tid + it * 256;
            int e  = qq >> 3;
            int kq = (qq & 7) * 4;
            float4 v = *reinterpret_cast<const float4*>(
                &W[(size_t)e * H + k0 + kq]);
            sm.g.ws[kq + 0][e] = v.x;
            sm.g.ws[kq + 1][e] = v.y;
            sm.g.ws[kq + 2][e] = v.z;
            sm.g.ws[kq + 3][e] = v.w;
        }
        __syncthreads();

        // ---- micro-kernel: 2 tokens x 8 experts per thread ----
#pragma unroll 8
        for (int k = 0; k < KB; k++) {
            float xv0 = sm.g.xs[r2 + 0][k];
            float xv1 = sm.g.xs[r2 + 1][k];
            float4 wa = *reinterpret_cast<const float4*>(&sm.g.ws[k][g8]);
            float4 wb = *reinterpret_cast<const float4*>(&sm.g.ws[k][g8 + 4]);
            acc[0][0] = fmaf(xv0, wa.x, acc[0][0]);
            acc[0][1] = fmaf(xv0, wa.y, acc[0][1]);
            acc[0][2] = fmaf(xv0, wa.z, acc[0][2]);
            acc[0][3] = fmaf(xv0, wa.w, acc[0][3]);
            acc[0][4] = fmaf(xv0, wb.x, acc[0][4]);
            acc[0][5] = fmaf(xv0, wb.y, acc[0][5]);
            acc[0][6] = fmaf(xv0, wb.z, acc[0][6]);
            acc[0][7] = fmaf(xv0, wb.w, acc[0][7]);
            acc[1][0] = fmaf(xv1, wa.x, acc[1][0]);
            acc[1][1] = fmaf(xv1, wa.y, acc[1][1]);
            acc[1][2] = fmaf(xv1, wa.z, acc[1][2]);
            acc[1][3] = fmaf(xv1, wa.w, acc[1][3]);
            acc[1][4] = fmaf(xv1, wb.x, acc[1][4]);
            acc[1][5] = fmaf(xv1, wb.y, acc[1][5]);
            acc[1][6] = fmaf(xv1, wb.z, acc[1][6]);
            acc[1][7] = fmaf(xv1, wb.w, acc[1][7]);
        }
        __syncthreads();
    }

    // ---- stash logits to smem for epilogue ----
#pragma unroll
    for (int i = 0; i < 2; i++)
#pragma unroll
        for (int e = 0; e < 8; e++)
            sm.ls[r2 + i][g8 + e] = acc[i][e];
    if (tid == 0) zsum = 0.0f;
    __syncthreads();

    // ---- per-token softmax / top-2 / outputs (64 token-threads) ----
    if (tid < TM) {
        const int t = tid;
        // top-2 scan; ties keep lower index (matches jax top_k)
        float v1 = -1e30f, v2 = -1e30f;
        int   i1 = 0,      i2 = 0;
#pragma unroll 4
        for (int e = 0; e < E; e++) {
            float le = sm.ls[t][e];
            if (le > v1)      { v2 = v1; i2 = i1; v1 = le; i1 = e; }
            else if (le > v2) { v2 = le; i2 = e; }
        }
        const float m = v1;
        float s = 0.0f;
#pragma unroll 4
        for (int e = 0; e < E; e++) {
            float p = expf(sm.ls[t][e] - m);
            sm.ls[t][e] = p;
            s += p;
        }
        const float inv = 1.0f / s;
#pragma unroll 4
        for (int e = 0; e < E; e++)
            sm.ls[t][e] *= inv;              // now holds softmax scores

        const float p1 = inv;                // exp(0)/s
        const float p2 = expf(v2 - m) * inv;
        // softmax over the two SCORE values (per reference)
        const float s1 = 1.0f / (1.0f + expf(p2 - p1));
        const float s2 = 1.0f - s1;

        const int tg = tok0 + t;
        out[tg * 2 + 0]         = s1;
        out[tg * 2 + 1]         = s2;
        out[2 * N + tg * 2 + 0] = (float)i1;
        out[2 * N + tg * 2 + 1] = (float)i2;

        const float lse = m + logf(s);
        atomicAdd(&zsum, lse * lse);
    }
    __syncthreads();

    // ---- expert-load column sums + global accumulation ----
    if (tid < E) {
        float cs = 0.0f;
#pragma unroll 8
        for (int t = 0; t < TM; t++) cs += sm.ls[t][tid];
        atomicAdd(&g_eload[tid], cs);
    }
    if (tid == 0) atomicAdd(&g_zsum, zsum);
}

__global__ void loss_kernel(float* __restrict__ out, int N) {
    __shared__ float sh[E];
    const int t = threadIdx.x;
    const float invN = 1.0f / (float)N;
    if (t < E) {
        float d = g_eload[t] * invN - (1.0f / 64.0f);
        sh[t] = d * d;
    }
    __syncthreads();
    if (t == 0) {
        float lb = 0.0f;
#pragma unroll
        for (int e = 0; e < E; e++) lb += sh[e];
        float loss = 0.01f * lb + 1e-4f * (g_zsum * invN);
        out[(size_t)4 * N] = loss;
    }
}

extern "C" void kernel_launch(void* const* d_in, const int* in_sizes, int n_in,
                              void* d_out, int out_size) {
    const float* x = (const float*)d_in[0];
    const float* W = (const float*)d_in[1];
    float* out = (float*)d_out;
    const int N = in_sizes[0] / H;   // 16384

    zero_kernel<<<1, 64>>>();
    gate_kernel<<<N / TM, THREADS>>>(x, W, out, N);
    loss_kernel<<<1, 64>>>(out, N);
}